// round 14
// baseline (speedup 1.0000x reference)
#include <cuda_runtime.h>
#include <cuda_fp16.h>
#include <cstdint>

// ---------------------------------------------------------------------------
// GraphConvolution: out[dst] += w_e * (X @ W)[src]
// R14: exact R13 + single change: GEMM tile 128x128 -> 64x128 (3 CTAs/SM,
//      24 warps) + one-shot W->fp16 conversion kernel feeding B loads.
// ---------------------------------------------------------------------------

#define N_NODES_MAX 100000
#define E_MAX       1600000
#define IN_F  256
#define OUT_F 128

__device__ __half g_support[(size_t)N_NODES_MAX * OUT_F];
__device__ __half g_wh[IN_F * OUT_F];
__device__ int    g_count[N_NODES_MAX];
__device__ int    g_offsets[N_NODES_MAX];
__device__ int    g_cursor[N_NODES_MAX];
__device__ uint2  g_edges[E_MAX];                  // (src, w bits), dst-bucketed
__device__ unsigned long long g_lb[64];            // lookback state (self-clean)
__device__ int    g_lb_done;                       // (self-clean)

// int64 edge_index <=> odd 32-bit words of the first 32 values are all zero
__device__ __forceinline__ int block_is64(const unsigned int* raw, int* sh)
{
    if (threadIdx.x == 0) {
        int is64 = 1;
        #pragma unroll
        for (int k = 1; k < 64; k += 2)
            if (raw[k] != 0u) { is64 = 0; break; }
        *sh = is64;
    }
    __syncthreads();
    return *sh;
}

// ---------------- histogram over dst ------------------------------------------
__global__ void hist_kernel(const unsigned int* __restrict__ raw, int E)
{
    __shared__ int sh_is64;
    const int is64 = block_is64(raw, &sh_is64);
    int e = blockIdx.x * blockDim.x + threadIdx.x;
    if (e >= E) return;
    int d = is64 ? (int)((const long long*)raw)[e] : ((const int*)raw)[e];
    atomicAdd(&g_count[d], 1);
}

// ---------------- single-pass decoupled-lookback exclusive scan ----------------
__global__ __launch_bounds__(1024) void scan_lb_kernel(int M)
{
    __shared__ int ws[32];
    __shared__ int s_excl;
    const int t    = threadIdx.x;
    const int lane = t & 31;
    const int wid  = t >> 5;
    const int bid  = blockIdx.x;
    const int base = bid * 4096 + t * 4;

    int v[4];
    if (base + 3 < M) {
        int4 lv = *reinterpret_cast<const int4*>(g_count + base);
        v[0] = lv.x; v[1] = lv.y; v[2] = lv.z; v[3] = lv.w;
    } else {
        #pragma unroll
        for (int q = 0; q < 4; q++) v[q] = (base + q < M) ? g_count[base + q] : 0;
    }
    const int tsum = v[0] + v[1] + v[2] + v[3];

    int incl = tsum;
    #pragma unroll
    for (int off = 1; off < 32; off <<= 1) {
        int x = __shfl_up_sync(0xffffffffu, incl, off);
        if (lane >= off) incl += x;
    }
    if (lane == 31) ws[wid] = incl;
    __syncthreads();
    if (wid == 0) {
        int s = ws[lane];
        #pragma unroll
        for (int off = 1; off < 32; off <<= 1) {
            int x = __shfl_up_sync(0xffffffffu, s, off);
            if (lane >= off) s += x;
        }
        ws[lane] = s;
    }
    __syncthreads();
    const int warpoff = (wid == 0) ? 0 : ws[wid - 1];
    const int texcl   = warpoff + incl - tsum;
    const int btotal  = ws[31];

    if (bid == 0) {
        if (t == 0) {
            atomicExch(&g_lb[0], (2ULL << 32) | (unsigned)btotal);
            s_excl = 0;
        }
    } else if (wid == 0) {
        if (lane == 0)
            atomicExch(&g_lb[bid], (1ULL << 32) | (unsigned)btotal);
        const int idx = bid - 1 - lane;
        int excl = 0;
        for (;;) {
            unsigned long long e = (idx >= 0)
                ? atomicAdd(&g_lb[idx], 0ULL)
                : (2ULL << 32);
            const unsigned st = (unsigned)(e >> 32);
            const unsigned bal_pub = __ballot_sync(0xffffffffu, st >= 1u);
            const unsigned bal_inc = __ballot_sync(0xffffffffu, st == 2u);
            if (bal_inc) {
                const int lstar = __ffs(bal_inc) - 1;
                const unsigned need = (lstar > 0) ? ((1u << lstar) - 1u) : 0u;
                if ((bal_pub & need) == need) {
                    int c = (lane <= lstar) ? (int)(unsigned)e : 0;
                    #pragma unroll
                    for (int off = 16; off >= 1; off >>= 1)
                        c += __shfl_xor_sync(0xffffffffu, c, off);
                    excl = c;
                    break;
                }
            }
        }
        if (lane == 0) {
            atomicExch(&g_lb[bid], (2ULL << 32) | (unsigned)(excl + btotal));
            s_excl = excl;
        }
    }
    __syncthreads();

    int ex = s_excl + texcl;
    #pragma unroll
    for (int q = 0; q < 4; q++) {
        if (base + q < M) { g_offsets[base + q] = ex; g_cursor[base + q] = ex; }
        ex += v[q];
    }

    __syncthreads();
    if (t == 0) {
        __threadfence();
        int d = atomicAdd(&g_lb_done, 1);
        if (d == gridDim.x - 1) {
            for (int i = 0; i < gridDim.x; i++) g_lb[i] = 0ULL;
            g_lb_done = 0;
            __threadfence();
        }
    }
}

// ---------------- place edges into dst buckets --------------------------------
__global__ void place_kernel(const unsigned int* __restrict__ raw,
                             const float* __restrict__ ew, int E)
{
    __shared__ int sh_is64;
    const int is64 = block_is64(raw, &sh_is64);
    int e = blockIdx.x * blockDim.x + threadIdx.x;
    if (e >= E) return;
    int d, s;
    if (is64) {
        const long long* ei = (const long long*)raw;
        d = (int)ei[e]; s = (int)ei[(size_t)E + e];
    } else {
        const int* ei = (const int*)raw;
        d = ei[e]; s = ei[(size_t)E + e];
    }
    int pos = atomicAdd(&g_cursor[d], 1);
    g_edges[pos] = make_uint2((unsigned)s, __float_as_uint(ew[e]));
}

// ---------------- W -> fp16 (one shot, tiny) -----------------------------------
__global__ void wcvt_kernel(const float* __restrict__ W)
{
    int i = blockIdx.x * blockDim.x + threadIdx.x;   // half2 index
    if (i >= IN_F * OUT_F / 2) return;
    float2 v = *reinterpret_cast<const float2*>(W + i * 2);
    *reinterpret_cast<__half2*>(g_wh + i * 2) = __floats2half2_rn(v.x, v.y);
}

// ---------------- fp16 mma helper ---------------------------------------------
__device__ __forceinline__ void mma_f16(
    float& c0, float& c1, float& c2, float& c3,
    uint32_t a0, uint32_t a1, uint32_t a2, uint32_t a3,
    uint32_t b0, uint32_t b1)
{
    asm volatile(
        "mma.sync.aligned.m16n8k16.row.col.f32.f16.f16.f32 "
        "{%0,%1,%2,%3}, {%4,%5,%6,%7}, {%8,%9}, {%0,%1,%2,%3};"
        : "+f"(c0), "+f"(c1), "+f"(c2), "+f"(c3)
        : "r"(a0), "r"(a1), "r"(a2), "r"(a3), "r"(b0), "r"(b1));
}

// ---------------- GEMM 64x128 CTA tile, fp16 mma, fp32 accum ------------------
// 8 warps as 2(M) x 4(N); warp tile 32x32 = 2 mi x 4 ni m16n8k16.
#define KC 64                 // k-chunk (halves)
#define PADH 72               // smem row stride in halves

__global__ __launch_bounds__(256) void gemm_mma_kernel(
    const float* __restrict__ X, __half* __restrict__ S, int M)
{
    __shared__ __half As[64][PADH];     // [m][k]
    __shared__ __half Bs[128][PADH];    // [n][k]

    const int t    = threadIdx.x;
    const int w    = t >> 5;
    const int lane = t & 31;
    const int g    = lane >> 2;
    const int tig  = lane & 3;
    const int wm   = (w & 1) * 32;
    const int wn   = (w >> 1) * 32;
    const int m0   = blockIdx.x * 64;

    float acc[2][4][4];
    #pragma unroll
    for (int mi = 0; mi < 2; mi++)
        #pragma unroll
        for (int ni = 0; ni < 4; ni++)
            #pragma unroll
            for (int r = 0; r < 4; r++) acc[mi][ni][r] = 0.0f;

    for (int k0 = 0; k0 < IN_F; k0 += KC) {
        // --- A: X[m0..+63][k0..+63] f32 -> half (1024 float4, 4/thread) ---
        #pragma unroll
        for (int i = 0; i < 4; i++) {
            int idx = t + i * 256;
            int r   = idx >> 4;                 // 16 float4 per 64-f32 row
            int c   = (idx & 15) * 4;
            float4 v = make_float4(0.f, 0.f, 0.f, 0.f);
            if (m0 + r < M)
                v = *reinterpret_cast<const float4*>(
                        X + (size_t)(m0 + r) * IN_F + k0 + c);
            *reinterpret_cast<__half2*>(&As[r][c])     = __floats2half2_rn(v.x, v.y);
            *reinterpret_cast<__half2*>(&As[r][c + 2]) = __floats2half2_rn(v.z, v.w);
        }
        // --- B: g_wh[k0+k][n] -> Bs[n][k] (4096 half2, 16/thread) ---
        #pragma unroll
        for (int i = 0; i < 16; i++) {
            int idx = t + i * 256;
            int k   = idx >> 6;                 // 64 half2 per 128-half row
            int n   = (idx & 63) * 2;
            __half2 h = *reinterpret_cast<const __half2*>(
                g_wh + (size_t)(k0 + k) * OUT_F + n);
            Bs[n][k]     = __low2half(h);
            Bs[n + 1][k] = __high2half(h);
        }
        __syncthreads();

        #pragma unroll
        for (int ks = 0; ks < KC / 16; ks++) {
            const int k = ks * 16;
            uint32_t a[2][4];
            #pragma unroll
            for (int mi = 0; mi < 2; mi++) {
                int mr = wm + mi * 16 + g;
                a[mi][0] = *reinterpret_cast<const uint32_t*>(&As[mr    ][k + tig * 2]);
                a[mi][1] = *reinterpret_cast<const uint32_t*>(&As[mr + 8][k + tig * 2]);
                a[mi][2] = *reinterpret_cast<const uint32_t*>(&As[mr    ][k + 8 + tig * 2]);
                a[mi][3] = *reinterpret_cast<const uint32_t*>(&As[mr + 8][k + 8 + tig * 2]);
            }
            uint32_t b[4][2];
            #pragma unroll
            for (int ni = 0; ni < 4; ni++) {
                int nr = wn + ni * 8 + g;
                b[ni][0] = *reinterpret_cast<const uint32_t*>(&Bs[nr][k + tig * 2]);
                b[ni][1] = *reinterpret_cast<const uint32_t*>(&Bs[nr][k + 8 + tig * 2]);
            }
            #pragma unroll
            for (int mi = 0; mi < 2; mi++)
                #pragma unroll
                for (int ni = 0; ni < 4; ni++)
                    mma_f16(acc[mi][ni][0], acc[mi][ni][1],
                            acc[mi][ni][2], acc[mi][ni][3],
                            a[mi][0], a[mi][1], a[mi][2], a[mi][3],
                            b[ni][0], b[ni][1]);
        }
        __syncthreads();
    }

    #pragma unroll
    for (int mi = 0; mi < 2; mi++) {
        int r0 = m0 + wm + mi * 16 + g;
        #pragma unroll
        for (int ni = 0; ni < 4; ni++) {
            int c = wn + ni * 8 + tig * 2;
            if (r0 < M)
                *reinterpret_cast<__half2*>(S + (size_t)r0 * OUT_F + c) =
                    __floats2half2_rn(acc[mi][ni][0], acc[mi][ni][1]);
            if (r0 + 8 < M)
                *reinterpret_cast<__half2*>(S + (size_t)(r0 + 8) * OUT_F + c) =
                    __floats2half2_rn(acc[mi][ni][2], acc[mi][ni][3]);
        }
    }
}

// ---------------- warp-per-node aggregation (R9 proven inner loop) ------------
__global__ __launch_bounds__(256) void aggregate_kernel(
    const __half* __restrict__ S, float* __restrict__ out, int M)
{
    const int node = (blockIdx.x * blockDim.x + threadIdx.x) >> 5;
    const int lane = threadIdx.x & 31;
    if (node >= M) return;

    const int start = g_offsets[node];
    const int cnt   = g_count[node];

    float4 acc0 = make_float4(0.f, 0.f, 0.f, 0.f);
    float4 acc1 = make_float4(0.f, 0.f, 0.f, 0.f);

    for (int b = 0; b < cnt; b += 32) {
        const int nb = (cnt - b < 32) ? (cnt - b) : 32;
        uint2 p = make_uint2(0u, 0u);
        if (lane < nb) p = g_edges[start + b + lane];

        int j = 0;
        for (; j + 4 <= nb; j += 4) {
            unsigned s0 = __shfl_sync(0xffffffffu, p.x, j);
            unsigned s1 = __shfl_sync(0xffffffffu, p.x, j + 1);
            unsigned s2 = __shfl_sync(0xffffffffu, p.x, j + 2);
            unsigned s3 = __shfl_sync(0xffffffffu, p.x, j + 3);
            float w0 = __uint_as_float(__shfl_sync(0xffffffffu, p.y, j));
            float w1 = __uint_as_float(__shfl_sync(0xffffffffu, p.y, j + 1));
            float w2 = __uint_as_float(__shfl_sync(0xffffffffu, p.y, j + 2));
            float w3 = __uint_as_float(__shfl_sync(0xffffffffu, p.y, j + 3));

            uint2 r0 = *reinterpret_cast<const uint2*>(S + (size_t)s0 * OUT_F + lane * 4);
            uint2 r1 = *reinterpret_cast<const uint2*>(S + (size_t)s1 * OUT_F + lane * 4);
            uint2 r2 = *reinterpret_cast<const uint2*>(S + (size_t)s2 * OUT_F + lane * 4);
            uint2 r3 = *reinterpret_cast<const uint2*>(S + (size_t)s3 * OUT_F + lane * 4);

            float2 a, bb;
            a  = __half22float2(*reinterpret_cast<__half2*>(&r0.x));
            bb = __half22float2(*reinterpret_cast<__half2*>(&r0.y));
            acc0.x = fmaf(w0, a.x,  acc0.x); acc0.y = fmaf(w0, a.y,  acc0.y);
            acc0.z = fmaf(w0, bb.x, acc0.z); acc0.w = fmaf(w0, bb.y, acc0.w);
            a  = __half22float2(*reinterpret_cast<__half2*>(&r1.x));
            bb = __half22float2(*reinterpret_cast<__half2*>(&r1.y));
            acc1.x = fmaf(w1, a.x,  acc1.x); acc1.y = fmaf(w1, a.y,  acc1.y);
            acc1.z = fmaf(w1, bb.x, acc1.z); acc1.w = fmaf(w1, bb.y, acc1.w);
            a  = __half22float2(*reinterpret_cast<__half2*>(&r2.x));
            bb = __half22float2(*reinterpret_cast<__half2*>(&r2.y));
            acc0.x = fmaf(w2, a.x,  acc0.x); acc0.y = fmaf(w2, a.y,  acc0.y);
            acc0.z = fmaf(w2, bb.x, acc0.z); acc0.w = fmaf(w2, bb.y, acc0.w);
            a  = __half22float2(*reinterpret_cast<__half2*>(&r3.x));
            bb = __half22float2(*reinterpret_cast<__half2*>(&r3.y));
            acc1.x = fmaf(w3, a.x,  acc1.x); acc1.y = fmaf(w3, a.y,  acc1.y);
            acc1.z = fmaf(w3, bb.x, acc1.z); acc1.w = fmaf(w3, bb.y, acc1.w);
        }
        for (; j < nb; j++) {
            unsigned sj = __shfl_sync(0xffffffffu, p.x, j);
            float    wj = __uint_as_float(__shfl_sync(0xffffffffu, p.y, j));
            uint2 r = *reinterpret_cast<const uint2*>(S + (size_t)sj * OUT_F + lane * 4);
            float2 a  = __half22float2(*reinterpret_cast<__half2*>(&r.x));
            float2 bb = __half22float2(*reinterpret_cast<__half2*>(&r.y));
            acc0.x = fmaf(wj, a.x,  acc0.x); acc0.y = fmaf(wj, a.y,  acc0.y);
            acc0.z = fmaf(wj, bb.x, acc0.z); acc0.w = fmaf(wj, bb.y, acc0.w);
        }
    }
    float4 r = make_float4(acc0.x + acc1.x, acc0.y + acc1.y,
                           acc0.z + acc1.z, acc0.w + acc1.w);
    *reinterpret_cast<float4*>(out + (size_t)node * OUT_F + lane * 4) = r;
}

// ---------------------------------------------------------------------------
extern "C" void kernel_launch(void* const* d_in, const int* in_sizes, int n_in,
                              void* d_out, int out_size)
{
    const float*        X  = (const float*)d_in[0];
    const unsigned int* EI = (const unsigned int*)d_in[1];
    const float*        EW = (const float*)d_in[2];
    const float*        W  = (const float*)d_in[3];
    float*              O  = (float*)d_out;

    const int M = out_size / OUT_F;
    const int E = in_sizes[2];

    __half* S;  cudaGetSymbolAddress((void**)&S, g_support);
    int*   CNT; cudaGetSymbolAddress((void**)&CNT, g_count);

    const int nbScan = (M + 4095) / 4096;

    cudaStream_t s2;
    cudaStreamCreateWithFlags(&s2, cudaStreamNonBlocking);
    cudaEvent_t evFork, evJoin;
    cudaEventCreateWithFlags(&evFork, cudaEventDisableTiming);
    cudaEventCreateWithFlags(&evJoin, cudaEventDisableTiming);

    cudaEventRecord(evFork, 0);
    cudaStreamWaitEvent(s2, evFork, 0);

    // --- branch B (s2): edge bucketing ---
    cudaMemsetAsync(CNT, 0, (size_t)M * sizeof(int), s2);
    hist_kernel<<<(E + 255) / 256, 256, 0, s2>>>(EI, E);
    scan_lb_kernel<<<nbScan, 1024, 0, s2>>>(M);
    place_kernel<<<(E + 255) / 256, 256, 0, s2>>>(EI, EW, E);
    cudaEventRecord(evJoin, s2);

    // --- branch A (default stream): W cvt + GEMM ---
    wcvt_kernel<<<(IN_F * OUT_F / 2 + 255) / 256, 256>>>(W);
    gemm_mma_kernel<<<(M + 63) / 64, 256>>>(X, S, M);

    // --- join, then aggregate ---
    cudaStreamWaitEvent(0, evJoin, 0);
    aggregate_kernel<<<(M * 32 + 255) / 256, 256>>>(S, O, M);

    cudaStreamDestroy(s2);
    cudaEventDestroy(evFork);
    cudaEventDestroy(evJoin);
}

// round 15
// speedup vs baseline: 1.2526x; 1.2526x over previous
#include <cuda_runtime.h>
#include <cuda_fp16.h>
#include <cstdint>

// ---------------------------------------------------------------------------
// GraphConvolution: out[dst] += w_e * (X @ W)[src]
// R15: exact R13 GEMM/aggregate/place; edge branch trimmed:
//      - memset removed (scan_lb zeroes g_count after reading)
//      - aggregate derives cnt from offsets[node+1]-offsets[node]
//      - hist processes 2 edges/thread
// ---------------------------------------------------------------------------

#define N_NODES_MAX 100000
#define E_MAX       1600000
#define IN_F  256
#define OUT_F 128

__device__ __half g_support[(size_t)N_NODES_MAX * OUT_F];
__device__ int    g_count[N_NODES_MAX];            // zero-init; re-zeroed by scan
__device__ int    g_offsets[N_NODES_MAX + 1];
__device__ int    g_cursor[N_NODES_MAX];
__device__ uint2  g_edges[E_MAX];                  // (src, w bits), dst-bucketed
__device__ unsigned long long g_lb[64];            // lookback state (self-clean)
__device__ int    g_lb_done;                       // (self-clean)

// int64 edge_index <=> odd 32-bit words of the first 32 values are all zero
__device__ __forceinline__ int block_is64(const unsigned int* raw, int* sh)
{
    if (threadIdx.x == 0) {
        int is64 = 1;
        #pragma unroll
        for (int k = 1; k < 64; k += 2)
            if (raw[k] != 0u) { is64 = 0; break; }
        *sh = is64;
    }
    __syncthreads();
    return *sh;
}

// ---------------- histogram over dst: 2 edges/thread ---------------------------
__global__ void hist_kernel(const unsigned int* __restrict__ raw, int E)
{
    __shared__ int sh_is64;
    const int is64 = block_is64(raw, &sh_is64);
    int e = (blockIdx.x * blockDim.x + threadIdx.x) * 2;
    if (e >= E) return;
    if (is64) {
        const long long* ei = (const long long*)raw;
        atomicAdd(&g_count[(int)ei[e]], 1);
        if (e + 1 < E) atomicAdd(&g_count[(int)ei[e + 1]], 1);
    } else {
        const int* ei = (const int*)raw;
        if (e + 1 < E) {
            int2 d2 = *reinterpret_cast<const int2*>(ei + e);
            atomicAdd(&g_count[d2.x], 1);
            atomicAdd(&g_count[d2.y], 1);
        } else {
            atomicAdd(&g_count[ei[e]], 1);
        }
    }
}

// ---------------- single-pass decoupled-lookback exclusive scan ----------------
// Also zeroes g_count (restores invariant) and writes g_offsets[M] = total.
__global__ __launch_bounds__(1024) void scan_lb_kernel(int M)
{
    __shared__ int ws[32];
    __shared__ int s_excl;
    const int t    = threadIdx.x;
    const int lane = t & 31;
    const int wid  = t >> 5;
    const int bid  = blockIdx.x;
    const int base = bid * 4096 + t * 4;

    int v[4];
    if (base + 3 < M) {
        int4 lv = *reinterpret_cast<const int4*>(g_count + base);
        v[0] = lv.x; v[1] = lv.y; v[2] = lv.z; v[3] = lv.w;
        *reinterpret_cast<int4*>(g_count + base) = make_int4(0, 0, 0, 0);
    } else {
        #pragma unroll
        for (int q = 0; q < 4; q++) {
            v[q] = (base + q < M) ? g_count[base + q] : 0;
            if (base + q < M) g_count[base + q] = 0;
        }
    }
    const int tsum = v[0] + v[1] + v[2] + v[3];

    int incl = tsum;
    #pragma unroll
    for (int off = 1; off < 32; off <<= 1) {
        int x = __shfl_up_sync(0xffffffffu, incl, off);
        if (lane >= off) incl += x;
    }
    if (lane == 31) ws[wid] = incl;
    __syncthreads();
    if (wid == 0) {
        int s = ws[lane];
        #pragma unroll
        for (int off = 1; off < 32; off <<= 1) {
            int x = __shfl_up_sync(0xffffffffu, s, off);
            if (lane >= off) s += x;
        }
        ws[lane] = s;
    }
    __syncthreads();
    const int warpoff = (wid == 0) ? 0 : ws[wid - 1];
    const int texcl   = warpoff + incl - tsum;
    const int btotal  = ws[31];

    if (bid == 0) {
        if (t == 0) {
            atomicExch(&g_lb[0], (2ULL << 32) | (unsigned)btotal);
            s_excl = 0;
        }
    } else if (wid == 0) {
        if (lane == 0)
            atomicExch(&g_lb[bid], (1ULL << 32) | (unsigned)btotal);
        const int idx = bid - 1 - lane;
        int excl = 0;
        for (;;) {
            unsigned long long e = (idx >= 0)
                ? atomicAdd(&g_lb[idx], 0ULL)
                : (2ULL << 32);
            const unsigned st = (unsigned)(e >> 32);
            const unsigned bal_pub = __ballot_sync(0xffffffffu, st >= 1u);
            const unsigned bal_inc = __ballot_sync(0xffffffffu, st == 2u);
            if (bal_inc) {
                const int lstar = __ffs(bal_inc) - 1;
                const unsigned need = (lstar > 0) ? ((1u << lstar) - 1u) : 0u;
                if ((bal_pub & need) == need) {
                    int c = (lane <= lstar) ? (int)(unsigned)e : 0;
                    #pragma unroll
                    for (int off = 16; off >= 1; off >>= 1)
                        c += __shfl_xor_sync(0xffffffffu, c, off);
                    excl = c;
                    break;
                }
            }
        }
        if (lane == 0) {
            atomicExch(&g_lb[bid], (2ULL << 32) | (unsigned)(excl + btotal));
            s_excl = excl;
        }
    }
    __syncthreads();

    int ex = s_excl + texcl;
    #pragma unroll
    for (int q = 0; q < 4; q++) {
        if (base + q < M) { g_offsets[base + q] = ex; g_cursor[base + q] = ex; }
        ex += v[q];
        if (base + q == M - 1) g_offsets[M] = ex;   // total
    }

    __syncthreads();
    if (t == 0) {
        __threadfence();
        int d = atomicAdd(&g_lb_done, 1);
        if (d == gridDim.x - 1) {
            for (int i = 0; i < gridDim.x; i++) g_lb[i] = 0ULL;
            g_lb_done = 0;
            __threadfence();
        }
    }
}

// ---------------- place edges into dst buckets --------------------------------
__global__ void place_kernel(const unsigned int* __restrict__ raw,
                             const float* __restrict__ ew, int E)
{
    __shared__ int sh_is64;
    const int is64 = block_is64(raw, &sh_is64);
    int e = blockIdx.x * blockDim.x + threadIdx.x;
    if (e >= E) return;
    int d, s;
    if (is64) {
        const long long* ei = (const long long*)raw;
        d = (int)ei[e]; s = (int)ei[(size_t)E + e];
    } else {
        const int* ei = (const int*)raw;
        d = ei[e]; s = ei[(size_t)E + e];
    }
    int pos = atomicAdd(&g_cursor[d], 1);
    g_edges[pos] = make_uint2((unsigned)s, __float_as_uint(ew[e]));
}

// ---------------- fp16 mma helper ---------------------------------------------
__device__ __forceinline__ void mma_f16(
    float& c0, float& c1, float& c2, float& c3,
    uint32_t a0, uint32_t a1, uint32_t a2, uint32_t a3,
    uint32_t b0, uint32_t b1)
{
    asm volatile(
        "mma.sync.aligned.m16n8k16.row.col.f32.f16.f16.f32 "
        "{%0,%1,%2,%3}, {%4,%5,%6,%7}, {%8,%9}, {%0,%1,%2,%3};"
        : "+f"(c0), "+f"(c1), "+f"(c2), "+f"(c3)
        : "r"(a0), "r"(a1), "r"(a2), "r"(a3), "r"(b0), "r"(b1));
}

// ---------------- GEMM 128x128 CTA tile, fp16 mma, fp32 accum (R13) -----------
#define KC 64                 // k-chunk (halves)
#define PADH 72               // smem row stride in halves

__global__ __launch_bounds__(256) void gemm_mma_kernel(
    const float* __restrict__ X, const float* __restrict__ W,
    __half* __restrict__ S, int M)
{
    __shared__ __half As[128][PADH];
    __shared__ __half Bs[128][PADH];

    const int t    = threadIdx.x;
    const int w    = t >> 5;
    const int lane = t & 31;
    const int g    = lane >> 2;
    const int tig  = lane & 3;
    const int wm   = (w & 3) * 32;
    const int wn   = (w >> 2) * 64;
    const int m0   = blockIdx.x * 128;

    float acc[2][8][4];
    #pragma unroll
    for (int mi = 0; mi < 2; mi++)
        #pragma unroll
        for (int ni = 0; ni < 8; ni++)
            #pragma unroll
            for (int r = 0; r < 4; r++) acc[mi][ni][r] = 0.0f;

    for (int k0 = 0; k0 < IN_F; k0 += KC) {
        #pragma unroll
        for (int i = 0; i < 8; i++) {
            int idx = t + i * 256;
            int r   = idx >> 4;
            int c   = (idx & 15) * 4;
            float4 v = make_float4(0.f, 0.f, 0.f, 0.f);
            if (m0 + r < M)
                v = *reinterpret_cast<const float4*>(
                        X + (size_t)(m0 + r) * IN_F + k0 + c);
            *reinterpret_cast<__half2*>(&As[r][c])     = __floats2half2_rn(v.x, v.y);
            *reinterpret_cast<__half2*>(&As[r][c + 2]) = __floats2half2_rn(v.z, v.w);
        }
        #pragma unroll
        for (int i = 0; i < 32; i++) {
            int idx = t + i * 256;
            int k   = idx >> 7;
            int n   = idx & 127;
            Bs[n][k] = __float2half_rn(W[(size_t)(k0 + k) * OUT_F + n]);
        }
        __syncthreads();

        #pragma unroll
        for (int ks = 0; ks < KC / 16; ks++) {
            const int k = ks * 16;
            uint32_t a[2][4];
            #pragma unroll
            for (int mi = 0; mi < 2; mi++) {
                int mr = wm + mi * 16 + g;
                a[mi][0] = *reinterpret_cast<const uint32_t*>(&As[mr    ][k + tig * 2]);
                a[mi][1] = *reinterpret_cast<const uint32_t*>(&As[mr + 8][k + tig * 2]);
                a[mi][2] = *reinterpret_cast<const uint32_t*>(&As[mr    ][k + 8 + tig * 2]);
                a[mi][3] = *reinterpret_cast<const uint32_t*>(&As[mr + 8][k + 8 + tig * 2]);
            }
            uint32_t b[8][2];
            #pragma unroll
            for (int ni = 0; ni < 8; ni++) {
                int nr = wn + ni * 8 + g;
                b[ni][0] = *reinterpret_cast<const uint32_t*>(&Bs[nr][k + tig * 2]);
                b[ni][1] = *reinterpret_cast<const uint32_t*>(&Bs[nr][k + 8 + tig * 2]);
            }
            #pragma unroll
            for (int mi = 0; mi < 2; mi++)
                #pragma unroll
                for (int ni = 0; ni < 8; ni++)
                    mma_f16(acc[mi][ni][0], acc[mi][ni][1],
                            acc[mi][ni][2], acc[mi][ni][3],
                            a[mi][0], a[mi][1], a[mi][2], a[mi][3],
                            b[ni][0], b[ni][1]);
        }
        __syncthreads();
    }

    #pragma unroll
    for (int mi = 0; mi < 2; mi++) {
        int r0 = m0 + wm + mi * 16 + g;
        #pragma unroll
        for (int ni = 0; ni < 8; ni++) {
            int c = wn + ni * 8 + tig * 2;
            if (r0 < M)
                *reinterpret_cast<__half2*>(S + (size_t)r0 * OUT_F + c) =
                    __floats2half2_rn(acc[mi][ni][0], acc[mi][ni][1]);
            if (r0 + 8 < M)
                *reinterpret_cast<__half2*>(S + (size_t)(r0 + 8) * OUT_F + c) =
                    __floats2half2_rn(acc[mi][ni][2], acc[mi][ni][3]);
        }
    }
}

// ---------------- warp-per-node aggregation (R9 loop; cnt from offsets) -------
__global__ __launch_bounds__(256) void aggregate_kernel(
    const __half* __restrict__ S, float* __restrict__ out, int M)
{
    const int node = (blockIdx.x * blockDim.x + threadIdx.x) >> 5;
    const int lane = threadIdx.x & 31;
    if (node >= M) return;

    const int start = g_offsets[node];
    const int cnt   = g_offsets[node + 1] - start;

    float4 acc0 = make_float4(0.f, 0.f, 0.f, 0.f);
    float4 acc1 = make_float4(0.f, 0.f, 0.f, 0.f);

    for (int b = 0; b < cnt; b += 32) {
        const int nb = (cnt - b < 32) ? (cnt - b) : 32;
        uint2 p = make_uint2(0u, 0u);
        if (lane < nb) p = g_edges[start + b + lane];

        int j = 0;
        for (; j + 4 <= nb; j += 4) {
            unsigned s0 = __shfl_sync(0xffffffffu, p.x, j);
            unsigned s1 = __shfl_sync(0xffffffffu, p.x, j + 1);
            unsigned s2 = __shfl_sync(0xffffffffu, p.x, j + 2);
            unsigned s3 = __shfl_sync(0xffffffffu, p.x, j + 3);
            float w0 = __uint_as_float(__shfl_sync(0xffffffffu, p.y, j));
            float w1 = __uint_as_float(__shfl_sync(0xffffffffu, p.y, j + 1));
            float w2 = __uint_as_float(__shfl_sync(0xffffffffu, p.y, j + 2));
            float w3 = __uint_as_float(__shfl_sync(0xffffffffu, p.y, j + 3));

            uint2 r0 = *reinterpret_cast<const uint2*>(S + (size_t)s0 * OUT_F + lane * 4);
            uint2 r1 = *reinterpret_cast<const uint2*>(S + (size_t)s1 * OUT_F + lane * 4);
            uint2 r2 = *reinterpret_cast<const uint2*>(S + (size_t)s2 * OUT_F + lane * 4);
            uint2 r3 = *reinterpret_cast<const uint2*>(S + (size_t)s3 * OUT_F + lane * 4);

            float2 a, bb;
            a  = __half22float2(*reinterpret_cast<__half2*>(&r0.x));
            bb = __half22float2(*reinterpret_cast<__half2*>(&r0.y));
            acc0.x = fmaf(w0, a.x,  acc0.x); acc0.y = fmaf(w0, a.y,  acc0.y);
            acc0.z = fmaf(w0, bb.x, acc0.z); acc0.w = fmaf(w0, bb.y, acc0.w);
            a  = __half22float2(*reinterpret_cast<__half2*>(&r1.x));
            bb = __half22float2(*reinterpret_cast<__half2*>(&r1.y));
            acc1.x = fmaf(w1, a.x,  acc1.x); acc1.y = fmaf(w1, a.y,  acc1.y);
            acc1.z = fmaf(w1, bb.x, acc1.z); acc1.w = fmaf(w1, bb.y, acc1.w);
            a  = __half22float2(*reinterpret_cast<__half2*>(&r2.x));
            bb = __half22float2(*reinterpret_cast<__half2*>(&r2.y));
            acc0.x = fmaf(w2, a.x,  acc0.x); acc0.y = fmaf(w2, a.y,  acc0.y);
            acc0.z = fmaf(w2, bb.x, acc0.z); acc0.w = fmaf(w2, bb.y, acc0.w);
            a  = __half22float2(*reinterpret_cast<__half2*>(&r3.x));
            bb = __half22float2(*reinterpret_cast<__half2*>(&r3.y));
            acc1.x = fmaf(w3, a.x,  acc1.x); acc1.y = fmaf(w3, a.y,  acc1.y);
            acc1.z = fmaf(w3, bb.x, acc1.z); acc1.w = fmaf(w3, bb.y, acc1.w);
        }
        for (; j < nb; j++) {
            unsigned sj = __shfl_sync(0xffffffffu, p.x, j);
            float    wj = __uint_as_float(__shfl_sync(0xffffffffu, p.y, j));
            uint2 r = *reinterpret_cast<const uint2*>(S + (size_t)sj * OUT_F + lane * 4);
            float2 a  = __half22float2(*reinterpret_cast<__half2*>(&r.x));
            float2 bb = __half22float2(*reinterpret_cast<__half2*>(&r.y));
            acc0.x = fmaf(wj, a.x,  acc0.x); acc0.y = fmaf(wj, a.y,  acc0.y);
            acc0.z = fmaf(wj, bb.x, acc0.z); acc0.w = fmaf(wj, bb.y, acc0.w);
        }
    }
    float4 r = make_float4(acc0.x + acc1.x, acc0.y + acc1.y,
                           acc0.z + acc1.z, acc0.w + acc1.w);
    *reinterpret_cast<float4*>(out + (size_t)node * OUT_F + lane * 4) = r;
}

// ---------------------------------------------------------------------------
extern "C" void kernel_launch(void* const* d_in, const int* in_sizes, int n_in,
                              void* d_out, int out_size)
{
    const float*        X  = (const float*)d_in[0];
    const unsigned int* EI = (const unsigned int*)d_in[1];
    const float*        EW = (const float*)d_in[2];
    const float*        W  = (const float*)d_in[3];
    float*              O  = (float*)d_out;

    const int M = out_size / OUT_F;
    const int E = in_sizes[2];

    __half* S; cudaGetSymbolAddress((void**)&S, g_support);

    const int nbScan = (M + 4095) / 4096;

    cudaStream_t s2;
    cudaStreamCreateWithFlags(&s2, cudaStreamNonBlocking);
    cudaEvent_t evFork, evJoin;
    cudaEventCreateWithFlags(&evFork, cudaEventDisableTiming);
    cudaEventCreateWithFlags(&evJoin, cudaEventDisableTiming);

    cudaEventRecord(evFork, 0);
    cudaStreamWaitEvent(s2, evFork, 0);

    // --- branch B (s2): edge bucketing (3 kernels, no memset) ---
    hist_kernel<<<(E / 2 + 255) / 256, 256, 0, s2>>>(EI, E);
    scan_lb_kernel<<<nbScan, 1024, 0, s2>>>(M);
    place_kernel<<<(E + 255) / 256, 256, 0, s2>>>(EI, EW, E);
    cudaEventRecord(evJoin, s2);

    // --- branch A (default stream): GEMM ---
    gemm_mma_kernel<<<(M + 127) / 128, 256>>>(X, W, S, M);

    // --- join, then aggregate ---
    cudaStreamWaitEvent(0, evJoin, 0);
    aggregate_kernel<<<(M * 32 + 255) / 256, 256>>>(S, O, M);

    cudaStreamDestroy(s2);
    cudaEventDestroy(evFork);
    cudaEventDestroy(evJoin);
}

// round 16
// speedup vs baseline: 1.3095x; 1.0454x over previous
#include <cuda_runtime.h>
#include <cuda_fp16.h>
#include <cstdint>

// ---------------------------------------------------------------------------
// GraphConvolution: out[dst] += w_e * (X @ W)[src]
// R16: exact R15 + single change: aggregate uses a dynamic node queue
//      (warps grab 8 nodes per atomic) to kill block-tail imbalance.
// ---------------------------------------------------------------------------

#define N_NODES_MAX 100000
#define E_MAX       1600000
#define IN_F  256
#define OUT_F 128
#define AGG_CHUNK 8

__device__ __half g_support[(size_t)N_NODES_MAX * OUT_F];
__device__ int    g_count[N_NODES_MAX];            // zero-init; re-zeroed by scan
__device__ int    g_offsets[N_NODES_MAX + 1];
__device__ int    g_cursor[N_NODES_MAX];
__device__ uint2  g_edges[E_MAX];                  // (src, w bits), dst-bucketed
__device__ unsigned long long g_lb[64];            // lookback state (self-clean)
__device__ int    g_lb_done;                       // (self-clean)
__device__ int    g_node_ctr;                      // agg work queue (reset by scan)

// int64 edge_index <=> odd 32-bit words of the first 32 values are all zero
__device__ __forceinline__ int block_is64(const unsigned int* raw, int* sh)
{
    if (threadIdx.x == 0) {
        int is64 = 1;
        #pragma unroll
        for (int k = 1; k < 64; k += 2)
            if (raw[k] != 0u) { is64 = 0; break; }
        *sh = is64;
    }
    __syncthreads();
    return *sh;
}

// ---------------- histogram over dst: 2 edges/thread ---------------------------
__global__ void hist_kernel(const unsigned int* __restrict__ raw, int E)
{
    __shared__ int sh_is64;
    const int is64 = block_is64(raw, &sh_is64);
    int e = (blockIdx.x * blockDim.x + threadIdx.x) * 2;
    if (e >= E) return;
    if (is64) {
        const long long* ei = (const long long*)raw;
        atomicAdd(&g_count[(int)ei[e]], 1);
        if (e + 1 < E) atomicAdd(&g_count[(int)ei[e + 1]], 1);
    } else {
        const int* ei = (const int*)raw;
        if (e + 1 < E) {
            int2 d2 = *reinterpret_cast<const int2*>(ei + e);
            atomicAdd(&g_count[d2.x], 1);
            atomicAdd(&g_count[d2.y], 1);
        } else {
            atomicAdd(&g_count[ei[e]], 1);
        }
    }
}

// ---------------- single-pass decoupled-lookback exclusive scan ----------------
// Also zeroes g_count, writes g_offsets[M]=total, resets the agg node queue.
__global__ __launch_bounds__(1024) void scan_lb_kernel(int M)
{
    __shared__ int ws[32];
    __shared__ int s_excl;
    const int t    = threadIdx.x;
    const int lane = t & 31;
    const int wid  = t >> 5;
    const int bid  = blockIdx.x;
    const int base = bid * 4096 + t * 4;

    if (bid == 0 && t == 0) g_node_ctr = 0;   // reset agg queue for this call

    int v[4];
    if (base + 3 < M) {
        int4 lv = *reinterpret_cast<const int4*>(g_count + base);
        v[0] = lv.x; v[1] = lv.y; v[2] = lv.z; v[3] = lv.w;
        *reinterpret_cast<int4*>(g_count + base) = make_int4(0, 0, 0, 0);
    } else {
        #pragma unroll
        for (int q = 0; q < 4; q++) {
            v[q] = (base + q < M) ? g_count[base + q] : 0;
            if (base + q < M) g_count[base + q] = 0;
        }
    }
    const int tsum = v[0] + v[1] + v[2] + v[3];

    int incl = tsum;
    #pragma unroll
    for (int off = 1; off < 32; off <<= 1) {
        int x = __shfl_up_sync(0xffffffffu, incl, off);
        if (lane >= off) incl += x;
    }
    if (lane == 31) ws[wid] = incl;
    __syncthreads();
    if (wid == 0) {
        int s = ws[lane];
        #pragma unroll
        for (int off = 1; off < 32; off <<= 1) {
            int x = __shfl_up_sync(0xffffffffu, s, off);
            if (lane >= off) s += x;
        }
        ws[lane] = s;
    }
    __syncthreads();
    const int warpoff = (wid == 0) ? 0 : ws[wid - 1];
    const int texcl   = warpoff + incl - tsum;
    const int btotal  = ws[31];

    if (bid == 0) {
        if (t == 0) {
            atomicExch(&g_lb[0], (2ULL << 32) | (unsigned)btotal);
            s_excl = 0;
        }
    } else if (wid == 0) {
        if (lane == 0)
            atomicExch(&g_lb[bid], (1ULL << 32) | (unsigned)btotal);
        const int idx = bid - 1 - lane;
        int excl = 0;
        for (;;) {
            unsigned long long e = (idx >= 0)
                ? atomicAdd(&g_lb[idx], 0ULL)
                : (2ULL << 32);
            const unsigned st = (unsigned)(e >> 32);
            const unsigned bal_pub = __ballot_sync(0xffffffffu, st >= 1u);
            const unsigned bal_inc = __ballot_sync(0xffffffffu, st == 2u);
            if (bal_inc) {
                const int lstar = __ffs(bal_inc) - 1;
                const unsigned need = (lstar > 0) ? ((1u << lstar) - 1u) : 0u;
                if ((bal_pub & need) == need) {
                    int c = (lane <= lstar) ? (int)(unsigned)e : 0;
                    #pragma unroll
                    for (int off = 16; off >= 1; off >>= 1)
                        c += __shfl_xor_sync(0xffffffffu, c, off);
                    excl = c;
                    break;
                }
            }
        }
        if (lane == 0) {
            atomicExch(&g_lb[bid], (2ULL << 32) | (unsigned)(excl + btotal));
            s_excl = excl;
        }
    }
    __syncthreads();

    int ex = s_excl + texcl;
    #pragma unroll
    for (int q = 0; q < 4; q++) {
        if (base + q < M) { g_offsets[base + q] = ex; g_cursor[base + q] = ex; }
        ex += v[q];
        if (base + q == M - 1) g_offsets[M] = ex;   // total
    }

    __syncthreads();
    if (t == 0) {
        __threadfence();
        int d = atomicAdd(&g_lb_done, 1);
        if (d == gridDim.x - 1) {
            for (int i = 0; i < gridDim.x; i++) g_lb[i] = 0ULL;
            g_lb_done = 0;
            __threadfence();
        }
    }
}

// ---------------- place edges into dst buckets --------------------------------
__global__ void place_kernel(const unsigned int* __restrict__ raw,
                             const float* __restrict__ ew, int E)
{
    __shared__ int sh_is64;
    const int is64 = block_is64(raw, &sh_is64);
    int e = blockIdx.x * blockDim.x + threadIdx.x;
    if (e >= E) return;
    int d, s;
    if (is64) {
        const long long* ei = (const long long*)raw;
        d = (int)ei[e]; s = (int)ei[(size_t)E + e];
    } else {
        const int* ei = (const int*)raw;
        d = ei[e]; s = ei[(size_t)E + e];
    }
    int pos = atomicAdd(&g_cursor[d], 1);
    g_edges[pos] = make_uint2((unsigned)s, __float_as_uint(ew[e]));
}

// ---------------- fp16 mma helper ---------------------------------------------
__device__ __forceinline__ void mma_f16(
    float& c0, float& c1, float& c2, float& c3,
    uint32_t a0, uint32_t a1, uint32_t a2, uint32_t a3,
    uint32_t b0, uint32_t b1)
{
    asm volatile(
        "mma.sync.aligned.m16n8k16.row.col.f32.f16.f16.f32 "
        "{%0,%1,%2,%3}, {%4,%5,%6,%7}, {%8,%9}, {%0,%1,%2,%3};"
        : "+f"(c0), "+f"(c1), "+f"(c2), "+f"(c3)
        : "r"(a0), "r"(a1), "r"(a2), "r"(a3), "r"(b0), "r"(b1));
}

// ---------------- GEMM 128x128 CTA tile, fp16 mma, fp32 accum (R13) -----------
#define KC 64                 // k-chunk (halves)
#define PADH 72               // smem row stride in halves

__global__ __launch_bounds__(256) void gemm_mma_kernel(
    const float* __restrict__ X, const float* __restrict__ W,
    __half* __restrict__ S, int M)
{
    __shared__ __half As[128][PADH];
    __shared__ __half Bs[128][PADH];

    const int t    = threadIdx.x;
    const int w    = t >> 5;
    const int lane = t & 31;
    const int g    = lane >> 2;
    const int tig  = lane & 3;
    const int wm   = (w & 3) * 32;
    const int wn   = (w >> 2) * 64;
    const int m0   = blockIdx.x * 128;

    float acc[2][8][4];
    #pragma unroll
    for (int mi = 0; mi < 2; mi++)
        #pragma unroll
        for (int ni = 0; ni < 8; ni++)
            #pragma unroll
            for (int r = 0; r < 4; r++) acc[mi][ni][r] = 0.0f;

    for (int k0 = 0; k0 < IN_F; k0 += KC) {
        #pragma unroll
        for (int i = 0; i < 8; i++) {
            int idx = t + i * 256;
            int r   = idx >> 4;
            int c   = (idx & 15) * 4;
            float4 v = make_float4(0.f, 0.f, 0.f, 0.f);
            if (m0 + r < M)
                v = *reinterpret_cast<const float4*>(
                        X + (size_t)(m0 + r) * IN_F + k0 + c);
            *reinterpret_cast<__half2*>(&As[r][c])     = __floats2half2_rn(v.x, v.y);
            *reinterpret_cast<__half2*>(&As[r][c + 2]) = __floats2half2_rn(v.z, v.w);
        }
        #pragma unroll
        for (int i = 0; i < 32; i++) {
            int idx = t + i * 256;
            int k   = idx >> 7;
            int n   = idx & 127;
            Bs[n][k] = __float2half_rn(W[(size_t)(k0 + k) * OUT_F + n]);
        }
        __syncthreads();

        #pragma unroll
        for (int ks = 0; ks < KC / 16; ks++) {
            const int k = ks * 16;
            uint32_t a[2][4];
            #pragma unroll
            for (int mi = 0; mi < 2; mi++) {
                int mr = wm + mi * 16 + g;
                a[mi][0] = *reinterpret_cast<const uint32_t*>(&As[mr    ][k + tig * 2]);
                a[mi][1] = *reinterpret_cast<const uint32_t*>(&As[mr + 8][k + tig * 2]);
                a[mi][2] = *reinterpret_cast<const uint32_t*>(&As[mr    ][k + 8 + tig * 2]);
                a[mi][3] = *reinterpret_cast<const uint32_t*>(&As[mr + 8][k + 8 + tig * 2]);
            }
            uint32_t b[8][2];
            #pragma unroll
            for (int ni = 0; ni < 8; ni++) {
                int nr = wn + ni * 8 + g;
                b[ni][0] = *reinterpret_cast<const uint32_t*>(&Bs[nr][k + tig * 2]);
                b[ni][1] = *reinterpret_cast<const uint32_t*>(&Bs[nr][k + 8 + tig * 2]);
            }
            #pragma unroll
            for (int mi = 0; mi < 2; mi++)
                #pragma unroll
                for (int ni = 0; ni < 8; ni++)
                    mma_f16(acc[mi][ni][0], acc[mi][ni][1],
                            acc[mi][ni][2], acc[mi][ni][3],
                            a[mi][0], a[mi][1], a[mi][2], a[mi][3],
                            b[ni][0], b[ni][1]);
        }
        __syncthreads();
    }

    #pragma unroll
    for (int mi = 0; mi < 2; mi++) {
        int r0 = m0 + wm + mi * 16 + g;
        #pragma unroll
        for (int ni = 0; ni < 8; ni++) {
            int c = wn + ni * 8 + tig * 2;
            if (r0 < M)
                *reinterpret_cast<__half2*>(S + (size_t)r0 * OUT_F + c) =
                    __floats2half2_rn(acc[mi][ni][0], acc[mi][ni][1]);
            if (r0 + 8 < M)
                *reinterpret_cast<__half2*>(S + (size_t)(r0 + 8) * OUT_F + c) =
                    __floats2half2_rn(acc[mi][ni][2], acc[mi][ni][3]);
        }
    }
}

// ---------------- aggregation: dynamic node queue, R9-proven inner loop -------
__global__ __launch_bounds__(256) void aggregate_kernel(
    const __half* __restrict__ S, float* __restrict__ out, int M)
{
    const int lane = threadIdx.x & 31;

    for (;;) {
        int n0;
        if (lane == 0) n0 = atomicAdd(&g_node_ctr, AGG_CHUNK);
        n0 = __shfl_sync(0xffffffffu, n0, 0);
        if (n0 >= M) return;
        const int n1 = (n0 + AGG_CHUNK < M) ? (n0 + AGG_CHUNK) : M;

        for (int node = n0; node < n1; node++) {
            const int start = g_offsets[node];
            const int cnt   = g_offsets[node + 1] - start;

            float4 acc0 = make_float4(0.f, 0.f, 0.f, 0.f);
            float4 acc1 = make_float4(0.f, 0.f, 0.f, 0.f);

            for (int b = 0; b < cnt; b += 32) {
                const int nb = (cnt - b < 32) ? (cnt - b) : 32;
                uint2 p = make_uint2(0u, 0u);
                if (lane < nb) p = g_edges[start + b + lane];

                int j = 0;
                for (; j + 4 <= nb; j += 4) {
                    unsigned s0 = __shfl_sync(0xffffffffu, p.x, j);
                    unsigned s1 = __shfl_sync(0xffffffffu, p.x, j + 1);
                    unsigned s2 = __shfl_sync(0xffffffffu, p.x, j + 2);
                    unsigned s3 = __shfl_sync(0xffffffffu, p.x, j + 3);
                    float w0 = __uint_as_float(__shfl_sync(0xffffffffu, p.y, j));
                    float w1 = __uint_as_float(__shfl_sync(0xffffffffu, p.y, j + 1));
                    float w2 = __uint_as_float(__shfl_sync(0xffffffffu, p.y, j + 2));
                    float w3 = __uint_as_float(__shfl_sync(0xffffffffu, p.y, j + 3));

                    uint2 r0 = *reinterpret_cast<const uint2*>(S + (size_t)s0 * OUT_F + lane * 4);
                    uint2 r1 = *reinterpret_cast<const uint2*>(S + (size_t)s1 * OUT_F + lane * 4);
                    uint2 r2 = *reinterpret_cast<const uint2*>(S + (size_t)s2 * OUT_F + lane * 4);
                    uint2 r3 = *reinterpret_cast<const uint2*>(S + (size_t)s3 * OUT_F + lane * 4);

                    float2 a, bb;
                    a  = __half22float2(*reinterpret_cast<__half2*>(&r0.x));
                    bb = __half22float2(*reinterpret_cast<__half2*>(&r0.y));
                    acc0.x = fmaf(w0, a.x,  acc0.x); acc0.y = fmaf(w0, a.y,  acc0.y);
                    acc0.z = fmaf(w0, bb.x, acc0.z); acc0.w = fmaf(w0, bb.y, acc0.w);
                    a  = __half22float2(*reinterpret_cast<__half2*>(&r1.x));
                    bb = __half22float2(*reinterpret_cast<__half2*>(&r1.y));
                    acc1.x = fmaf(w1, a.x,  acc1.x); acc1.y = fmaf(w1, a.y,  acc1.y);
                    acc1.z = fmaf(w1, bb.x, acc1.z); acc1.w = fmaf(w1, bb.y, acc1.w);
                    a  = __half22float2(*reinterpret_cast<__half2*>(&r2.x));
                    bb = __half22float2(*reinterpret_cast<__half2*>(&r2.y));
                    acc0.x = fmaf(w2, a.x,  acc0.x); acc0.y = fmaf(w2, a.y,  acc0.y);
                    acc0.z = fmaf(w2, bb.x, acc0.z); acc0.w = fmaf(w2, bb.y, acc0.w);
                    a  = __half22float2(*reinterpret_cast<__half2*>(&r3.x));
                    bb = __half22float2(*reinterpret_cast<__half2*>(&r3.y));
                    acc1.x = fmaf(w3, a.x,  acc1.x); acc1.y = fmaf(w3, a.y,  acc1.y);
                    acc1.z = fmaf(w3, bb.x, acc1.z); acc1.w = fmaf(w3, bb.y, acc1.w);
                }
                for (; j < nb; j++) {
                    unsigned sj = __shfl_sync(0xffffffffu, p.x, j);
                    float    wj = __uint_as_float(__shfl_sync(0xffffffffu, p.y, j));
                    uint2 r = *reinterpret_cast<const uint2*>(S + (size_t)sj * OUT_F + lane * 4);
                    float2 a  = __half22float2(*reinterpret_cast<__half2*>(&r.x));
                    float2 bb = __half22float2(*reinterpret_cast<__half2*>(&r.y));
                    acc0.x = fmaf(wj, a.x,  acc0.x); acc0.y = fmaf(wj, a.y,  acc0.y);
                    acc0.z = fmaf(wj, bb.x, acc0.z); acc0.w = fmaf(wj, bb.y, acc0.w);
                }
            }
            float4 r = make_float4(acc0.x + acc1.x, acc0.y + acc1.y,
                                   acc0.z + acc1.z, acc0.w + acc1.w);
            *reinterpret_cast<float4*>(out + (size_t)node * OUT_F + lane * 4) = r;
        }
    }
}

// ---------------------------------------------------------------------------
extern "C" void kernel_launch(void* const* d_in, const int* in_sizes, int n_in,
                              void* d_out, int out_size)
{
    const float*        X  = (const float*)d_in[0];
    const unsigned int* EI = (const unsigned int*)d_in[1];
    const float*        EW = (const float*)d_in[2];
    const float*        W  = (const float*)d_in[3];
    float*              O  = (float*)d_out;

    const int M = out_size / OUT_F;
    const int E = in_sizes[2];

    __half* S; cudaGetSymbolAddress((void**)&S, g_support);

    const int nbScan = (M + 4095) / 4096;

    cudaStream_t s2;
    cudaStreamCreateWithFlags(&s2, cudaStreamNonBlocking);
    cudaEvent_t evFork, evJoin;
    cudaEventCreateWithFlags(&evFork, cudaEventDisableTiming);
    cudaEventCreateWithFlags(&evJoin, cudaEventDisableTiming);

    cudaEventRecord(evFork, 0);
    cudaStreamWaitEvent(s2, evFork, 0);

    // --- branch B (s2): edge bucketing (3 kernels, no memset) ---
    hist_kernel<<<(E / 2 + 255) / 256, 256, 0, s2>>>(EI, E);
    scan_lb_kernel<<<nbScan, 1024, 0, s2>>>(M);
    place_kernel<<<(E + 255) / 256, 256, 0, s2>>>(EI, EW, E);
    cudaEventRecord(evJoin, s2);

    // --- branch A (default stream): GEMM ---
    gemm_mma_kernel<<<(M + 127) / 128, 256>>>(X, W, S, M);

    // --- join, then aggregate (persistent-ish grid, dynamic queue) ---
    cudaStreamWaitEvent(0, evJoin, 0);
    aggregate_kernel<<<1184, 256>>>(S, O, M);

    cudaStreamDestroy(s2);
    cudaEventDestroy(evFork);
    cudaEventDestroy(evJoin);
}